// round 13
// baseline (speedup 1.0000x reference)
#include <cuda_runtime.h>
#include <cstdint>

// EmbeddingBagCollection: T=8 tables [V=100000, D=128] fp32, indices [T,B=4096,L=50] int32.
// out[b, t*D + d] = sum_{l} tables[t, indices[t,b,l], d]
//
// Persistent grid (592 CTAs = 148 SM x 4), warp-per-bag, 7 bags/warp, table-major
// (each iteration's bag window spans ~1.16 tables -> L2 dedup keeps DRAM at the
// compulsory floor ~386 MB).
// KEY CHANGE vs R11: software pipeline on index loads — bag(it+1)'s 50 indices
// are loaded into registers BEFORE bag(it)'s gathers execute, so the idx-load
// latency hides under the 50-row gather stream (removes the per-bag MLP=0 bubble).
// Rows: 10-deep batched ld.global.cg.v4. Output: streaming st.global.cs.

#define T_TABLES 8
#define B_BATCH  4096
#define L_BAG    50
#define V_VOCAB  100000
#define D_DIM    128
#define CHUNK    10
#define NUM_CTAS 592
#define WARPS_PER_BLOCK 8
#define TOTAL_BAGS (T_TABLES * B_BATCH)             // 32768
#define WARP_SLOTS (NUM_CTAS * WARPS_PER_BLOCK)     // 4736
#define NUM_ITERS  ((TOTAL_BAGS + WARP_SLOTS - 1) / WARP_SLOTS)  // 7

__device__ __forceinline__ float4 ldg_cg_f4(const float* p) {
    float4 v;
    asm volatile("ld.global.cg.v4.f32 {%0,%1,%2,%3}, [%4];"
                 : "=f"(v.x), "=f"(v.y), "=f"(v.z), "=f"(v.w)
                 : "l"(p));
    return v;
}

__device__ __forceinline__ void stg_cs_f4(float* p, float4 v) {
    asm volatile("st.global.cs.v4.f32 [%0], {%1,%2,%3,%4};"
                 :: "l"(p), "f"(v.x), "f"(v.y), "f"(v.z), "f"(v.w)
                 : "memory");
}

__global__ void __launch_bounds__(256, 4)
ebc_kernel(const int*   __restrict__ indices,
           const float* __restrict__ tables,
           float*       __restrict__ out)
{
    const int lane  = threadIdx.x & 31;
    const int gwarp = blockIdx.x * WARPS_PER_BLOCK + (threadIdx.x >> 5);

    // Prologue: load indices for the first bag (2 coalesced LDGs/warp).
    int i0, i1;
    {
        const int* __restrict__ bag = indices + (size_t)gwarp * L_BAG;
        i0 = bag[lane];
        i1 = (lane < L_BAG - 32) ? bag[32 + lane] : 0;
    }

    #pragma unroll 1
    for (int it = 0; it < NUM_ITERS; ++it) {
        const int bag_id = it * WARP_SLOTS + gwarp;
        if (bag_id >= TOTAL_BAGS) return;   // only last iteration can exit

        // ---- Prefetch next bag's indices (latency hides under gathers below).
        int n0 = 0, n1 = 0;
        const int next_bag = bag_id + WARP_SLOTS;
        if (next_bag < TOTAL_BAGS) {
            const int* __restrict__ nbag = indices + (size_t)next_bag * L_BAG;
            n0 = nbag[lane];
            n1 = (lane < L_BAG - 32) ? nbag[32 + lane] : 0;
        }

        const int t = bag_id / B_BATCH;     // table id (table-major)
        const int b = bag_id % B_BATCH;     // bag id

        const float* __restrict__ tab = tables + (size_t)t * V_VOCAB * D_DIM
                                               + (size_t)lane * 4;

        float4 acc = make_float4(0.f, 0.f, 0.f, 0.f);

        #pragma unroll
        for (int base = 0; base < L_BAG; base += CHUNK) {
            float4 v[CHUNK];
            #pragma unroll
            for (int j = 0; j < CHUNK; ++j) {
                const int jj = base + j;                    // compile-time
                const int r  = (jj < 32)
                             ? __shfl_sync(0xffffffffu, i0, jj)
                             : __shfl_sync(0xffffffffu, i1, jj - 32);
                v[j] = ldg_cg_f4(tab + (size_t)r * D_DIM);
            }
            #pragma unroll
            for (int j = 0; j < CHUNK; ++j) {
                acc.x += v[j].x;
                acc.y += v[j].y;
                acc.z += v[j].z;
                acc.w += v[j].w;
            }
        }

        stg_cs_f4(out + (size_t)b * (T_TABLES * D_DIM) + t * D_DIM + lane * 4, acc);

        i0 = n0;
        i1 = n1;
    }
}

extern "C" void kernel_launch(void* const* d_in, const int* in_sizes, int n_in,
                              void* d_out, int out_size)
{
    const long long N_IDX = (long long)T_TABLES * B_BATCH * L_BAG;

    const int*   indices;
    const float* tables;
    if ((long long)in_sizes[0] == N_IDX) {
        indices = (const int*)d_in[0];
        tables  = (const float*)d_in[1];
    } else {
        indices = (const int*)d_in[1];
        tables  = (const float*)d_in[0];
    }
    float* out = (float*)d_out;

    ebc_kernel<<<NUM_CTAS, 256>>>(indices, tables, out);
}

// round 14
// speedup vs baseline: 1.0615x; 1.0615x over previous
#include <cuda_runtime.h>
#include <cstdint>

// EmbeddingBagCollection: T=8 tables [V=100000, D=128] fp32, indices [T,B=4096,L=50] int32.
// out[b, t*D + d] = sum_{l} tables[t, indices[t,b,l], d]
//
// Champion config (R4) with warp-private index staging:
//  - one warp per bag, lane owns float4 of the D=128 row, table-major bag order
//    (resident wave spans ~1.2 tables -> L2 dedup -> compulsory DRAM traffic ~386MB)
//  - each warp stages its OWN 50 indices smem via 2 coalesced LDG + STS + __syncwarp
//    (no __syncthreads, no cross-warp coupling, no shfl ALU tax)
//  - gather loop: 10 independent ld.global.cg.v4 in flight per warp (L2-only)
//  - output: streaming st.global.cs (don't evict live table rows from L2)

#define T_TABLES 8
#define B_BATCH  4096
#define L_BAG    50
#define V_VOCAB  100000
#define D_DIM    128
#define CHUNK    10
#define WARPS_PER_BLOCK 8

__device__ __forceinline__ float4 ldg_cg_f4(const float* p) {
    float4 v;
    asm volatile("ld.global.cg.v4.f32 {%0,%1,%2,%3}, [%4];"
                 : "=f"(v.x), "=f"(v.y), "=f"(v.z), "=f"(v.w)
                 : "l"(p));
    return v;
}

__device__ __forceinline__ void stg_cs_f4(float* p, float4 v) {
    asm volatile("st.global.cs.v4.f32 [%0], {%1,%2,%3,%4};"
                 :: "l"(p), "f"(v.x), "f"(v.y), "f"(v.z), "f"(v.w)
                 : "memory");
}

__global__ void __launch_bounds__(256, 4)
ebc_kernel(const int*   __restrict__ indices,
           const float* __restrict__ tables,
           float*       __restrict__ out)
{
    __shared__ int s_idx[WARPS_PER_BLOCK * 64];   // 64-int slice per warp (pad: no bank aliasing)

    const int tid     = threadIdx.x;
    const int lane    = tid & 31;
    const int wslot   = tid >> 5;
    const int warp_id = blockIdx.x * WARPS_PER_BLOCK + wslot;

    // Warp-private staging: this warp's 50 indices, 2 coalesced LDGs -> STS.
    {
        const int* __restrict__ bag = indices + (size_t)warp_id * L_BAG;
        int* s = s_idx + wslot * 64;
        s[lane] = bag[lane];
        if (lane < L_BAG - 32)
            s[32 + lane] = bag[32 + lane];
    }
    __syncwarp();

    const int t = warp_id / B_BATCH;   // table id (table-major => L2 locality)
    const int b = warp_id % B_BATCH;   // bag id

    const int* bag = s_idx + wslot * 64;
    const float* __restrict__ tab = tables + (size_t)t * V_VOCAB * D_DIM
                                           + (size_t)lane * 4;

    float4 acc = make_float4(0.f, 0.f, 0.f, 0.f);

    #pragma unroll
    for (int base = 0; base < L_BAG; base += CHUNK) {
        float4 v[CHUNK];
        #pragma unroll
        for (int j = 0; j < CHUNK; ++j) {
            const int r = bag[base + j];               // LDS broadcast
            v[j] = ldg_cg_f4(tab + (size_t)r * D_DIM); // L2-only gather
        }
        #pragma unroll
        for (int j = 0; j < CHUNK; ++j) {
            acc.x += v[j].x;
            acc.y += v[j].y;
            acc.z += v[j].z;
            acc.w += v[j].w;
        }
    }

    stg_cs_f4(out + (size_t)b * (T_TABLES * D_DIM) + t * D_DIM + lane * 4, acc);
}

extern "C" void kernel_launch(void* const* d_in, const int* in_sizes, int n_in,
                              void* d_out, int out_size)
{
    const long long N_IDX = (long long)T_TABLES * B_BATCH * L_BAG;

    const int*   indices;
    const float* tables;
    if ((long long)in_sizes[0] == N_IDX) {
        indices = (const int*)d_in[0];
        tables  = (const float*)d_in[1];
    } else {
        indices = (const int*)d_in[1];
        tables  = (const float*)d_in[0];
    }
    float* out = (float*)d_out;

    const int total_warps = T_TABLES * B_BATCH;              // 32768 bags
    const int blocks      = total_warps / WARPS_PER_BLOCK;   // 4096 blocks

    ebc_kernel<<<blocks, 256>>>(indices, tables, out);
}